// round 14
// baseline (speedup 1.0000x reference)
#include <cuda_runtime.h>
#include <cuda_bf16.h>

// AbsDiff cost volume:
//   out[n, d, y, x] = |image1[n,0,y,x] - image2[n,0,y,x-d]|  if x-d >= 0 else 0
// in [2,1,384,1248] fp32, out [2,128,384,1248] fp32. HBM-write-bound (~491MB).
// R14: chain-4 stores (R13's win) WITHOUT R13's doubled input reads. One CTA
// per (n,y,d-chunk-of-8): right row staged in smem once; 640 threads in two
// groups of 320, group g handles d0+4g..d0+4g+3. Per-thread store chain = 4,
// input L2 traffic back to the 16-chunk level, 60 warps/SM at occ 3.

#define W_DIM    1248
#define H_DIM    384
#define N_DIM    2
#define D_DIM    128
#define W4       (W_DIM / 4)          // 312
#define GROUP    320                  // threads per d-group; >= W4
#define THREADS  (2 * GROUP)          // 640 = 20 warps
#define D_SPLIT  16
#define D_CHUNK  (D_DIM / D_SPLIT)    // 8 per CTA; 4 per thread-group
#define PAD      128                  // leading zeros: x-d never underflows

__device__ __forceinline__ void stcs4(float4* p, float4 v) {
    asm volatile("st.global.cs.v4.f32 [%0], {%1,%2,%3,%4};"
                 :: "l"(p), "f"(v.x), "f"(v.y), "f"(v.z), "f"(v.w) : "memory");
}

__global__ __launch_bounds__(THREADS, 3)
void absdiff_costvol_kernel(const float* __restrict__ left,
                            const float* __restrict__ right,
                            float* __restrict__ out)
{
    __shared__ float4 sr4[(PAD + W_DIM) / 4];   // 344 float4 = 5.5 KB

    const int nh = blockIdx.x;                  // n*H + y   (768)
    const int d0 = blockIdx.y * D_CHUNK;        // multiple of 8
    const int t  = threadIdx.x;
    const int g  = t / GROUP;                   // d-group: 0 or 1
    const int u  = t % GROUP;                   // lane within group

    const float4* rrow4 = (const float4*)(right + (size_t)nh * W_DIM);
    const float4* lrow4 = (const float4*)(left  + (size_t)nh * W_DIM);

    // Stage: zeros in the pad, right row after it (first group only).
    if (t < PAD / 4)
        sr4[t] = make_float4(0.f, 0.f, 0.f, 0.f);
    else if (t >= GROUP && t - GROUP < W4)      // second group stages the row
        sr4[PAD / 4 + (t - GROUP)] = rrow4[t - GROUP];

    float4 L = make_float4(0.f, 0.f, 0.f, 0.f);
    if (u < W4)
        L = lrow4[u];                            // group 1 hits L1 on these

    __syncthreads();

    const int n = nh / H_DIM;
    const int y = nh % H_DIM;
    float* ob = out + ((size_t)(n * D_DIM + d0) * H_DIM + y) * W_DIM;

    if (u < W4) {
        const int dbase = d0 + 4 * g;           // this group's first d, %4==0
        const int x0 = 4 * u;
        const int c0 = PAD - dbase + x0;        // smem float idx of R[x0-dbase]
        const int b4 = c0 >> 2;                 // >= 1 always (c0 >= 4)

        // Window: floats [c0-4, c0+3] cover all 4 shifted reads of this group.
        float w[8];
        {
            const float4 X = sr4[b4 - 1];
            const float4 Y = sr4[b4];
            w[0]=X.x; w[1]=X.y; w[2]=X.z; w[3]=X.w;
            w[4]=Y.x; w[5]=Y.y; w[6]=Y.z; w[7]=Y.w;
        }

        float* og = ob + (size_t)(4 * g) * (H_DIM * W_DIM);

        #pragma unroll
        for (int k = 0; k < 4; ++k) {
            const int d  = dbase + k;
            const int j0 = 4 - k;               // compile-time window offset

            float4 v;
            v.x = (x0 + 0 >= d) ? fabsf(L.x - w[j0 + 0]) : 0.f;
            v.y = (x0 + 1 >= d) ? fabsf(L.y - w[j0 + 1]) : 0.f;
            v.z = (x0 + 2 >= d) ? fabsf(L.z - w[j0 + 2]) : 0.f;
            v.w = (x0 + 3 >= d) ? fabsf(L.w - w[j0 + 3]) : 0.f;

            stcs4((float4*)(og + (size_t)k * (H_DIM * W_DIM)) + u, v);
        }
    }
}

extern "C" void kernel_launch(void* const* d_in, const int* in_sizes, int n_in,
                              void* d_out, int out_size)
{
    const float* image1 = (const float*)d_in[0];  // left
    const float* image2 = (const float*)d_in[1];  // right (shifted source)
    float* out = (float*)d_out;

    (void)in_sizes; (void)n_in; (void)out_size;

    dim3 grid(N_DIM * H_DIM, D_SPLIT);   // 768 x 16 = 12288 blocks
    dim3 block(THREADS);
    absdiff_costvol_kernel<<<grid, block>>>(image1, image2, out);
}

// round 15
// speedup vs baseline: 1.0470x; 1.0470x over previous
#include <cuda_runtime.h>
#include <cuda_bf16.h>

// AbsDiff cost volume:
//   out[n, d, y, x] = |image1[n,0,y,x] - image2[n,0,y,x-d]|  if x-d >= 0 else 0
// in [2,1,384,1248] fp32, out [2,128,384,1248] fp32. HBM-write-bound (~491MB).
// R15 = R13 (best: no-smem chain-4 stores, 256thr occ8) with grid dims
// SWAPPED so the d-chunk index varies fastest across CTA ranks: the 32 CTAs
// re-reading the same input rows run back-to-back on nearby SMs -> input
// loads become L1-hits instead of L2 round-trips, cutting L2 read traffic
// ~8x while the store stream is unchanged.

#define W_DIM    1248
#define H_DIM    384
#define N_DIM    2
#define D_DIM    128
#define W4       (W_DIM / 4)          // 312
#define THREADS  256
#define D_CHUNK  4                    // per-thread store chain
#define D_BLKS   (D_DIM / D_CHUNK)    // 32
#define XY_BLKS  ((N_DIM * H_DIM * W4) / THREADS)   // 936, exact

__device__ __forceinline__ void stcs4(float4* p, float4 v) {
    asm volatile("st.global.cs.v4.f32 [%0], {%1,%2,%3,%4};"
                 :: "l"(p), "f"(v.x), "f"(v.y), "f"(v.z), "f"(v.w) : "memory");
}

__global__ __launch_bounds__(THREADS, 8)
void absdiff_costvol_kernel(const float* __restrict__ left,
                            const float* __restrict__ right,
                            float* __restrict__ out)
{
    // d-chunk on blockIdx.x (fastest-varying rank) -> CTAs sharing input
    // rows are temporally adjacent -> L1-resident input re-reads.
    const int gid = blockIdx.y * THREADS + threadIdx.x;   // xy flat, < 239616
    const int x4  = gid % W4;
    const int ny  = gid / W4;                             // n*H + y, < 768
    const int d0  = blockIdx.x * D_CHUNK;                 // multiple of 4

    const int x0 = 4 * x4;

    // Left float4 (always in-bounds, aligned).
    const float4 L = reinterpret_cast<const float4*>(
                         left + (size_t)ny * W_DIM)[x4];

    // Window: floats [x0-d0-4, x0-d0+3] of the right row (blocks b, b+1).
    // Covers R[x0-d .. x0+3-d] for d in [d0, d0+3]. Negative blocks clamp
    // to 0 — clamped values feed only mask-zeroed outputs (x < d there).
    const float4* rrow4 = reinterpret_cast<const float4*>(
                              right + (size_t)ny * W_DIM);
    const int b  = x4 - d0 / 4 - 1;      // may be negative, <= 310
    const int b0 = b     < 0 ? 0 : b;
    const int b1 = b + 1 < 0 ? 0 : b + 1;

    float w[8];
    {
        const float4 X = rrow4[b0];
        const float4 Y = rrow4[b1];
        w[0]=X.x; w[1]=X.y; w[2]=X.z; w[3]=X.w;
        w[4]=Y.x; w[5]=Y.y; w[6]=Y.z; w[7]=Y.w;
    }

    const int n = ny / H_DIM;
    const int y = ny % H_DIM;
    float* ob = out + ((size_t)(n * D_DIM + d0) * H_DIM + y) * W_DIM + x0;

    #pragma unroll
    for (int k = 0; k < D_CHUNK; ++k) {
        const int d  = d0 + k;
        const int j0 = 4 - k;            // compile-time window offset

        float4 v;
        v.x = (x0 + 0 >= d) ? fabsf(L.x - w[j0 + 0]) : 0.f;
        v.y = (x0 + 1 >= d) ? fabsf(L.y - w[j0 + 1]) : 0.f;
        v.z = (x0 + 2 >= d) ? fabsf(L.z - w[j0 + 2]) : 0.f;
        v.w = (x0 + 3 >= d) ? fabsf(L.w - w[j0 + 3]) : 0.f;

        stcs4((float4*)(ob + (size_t)k * (H_DIM * W_DIM)), v);
    }
}

extern "C" void kernel_launch(void* const* d_in, const int* in_sizes, int n_in,
                              void* d_out, int out_size)
{
    const float* image1 = (const float*)d_in[0];  // left
    const float* image2 = (const float*)d_in[1];  // right (shifted source)
    float* out = (float*)d_out;

    (void)in_sizes; (void)n_in; (void)out_size;

    dim3 grid(D_BLKS, XY_BLKS);   // 32 x 936 = 29952 blocks, d fastest
    dim3 block(THREADS);
    absdiff_costvol_kernel<<<grid, block>>>(image1, image2, out);
}

// round 16
// speedup vs baseline: 1.0533x; 1.0060x over previous
#include <cuda_runtime.h>
#include <cuda_bf16.h>

// AbsDiff cost volume:
//   out[n, d, y, x] = |image1[n,0,y,x] - image2[n,0,y,x-d]|  if x-d >= 0 else 0
// in [2,1,384,1248] fp32, out [2,128,384,1248] fp32. HBM-write-bound (~491MB).
// R16 = R13 (champion: chain-4 STG.128 .cs, no smem/sync, xy-fastest CTA
// order -> concurrent CTAs write contiguous DRAM) with 512-thread CTAs at
// occ 4: same 2048 thr/SM and identical traversal, half the CTA churn.
// (R15 proved rank order is load-bearing: d-fastest killed DRAM page
// locality, 80.6% -> 74.1%. Keep xy fastest.)

#define W_DIM    1248
#define H_DIM    384
#define N_DIM    2
#define D_DIM    128
#define W4       (W_DIM / 4)          // 312
#define THREADS  512
#define D_CHUNK  4                    // per-thread store chain (16->71.8,
                                      // 8->69.7, 4->69.15 us measured)
#define XY_BLKS  ((N_DIM * H_DIM * W4) / THREADS)   // 468, exact

__device__ __forceinline__ void stcs4(float4* p, float4 v) {
    asm volatile("st.global.cs.v4.f32 [%0], {%1,%2,%3,%4};"
                 :: "l"(p), "f"(v.x), "f"(v.y), "f"(v.z), "f"(v.w) : "memory");
}

__global__ __launch_bounds__(THREADS, 4)
void absdiff_costvol_kernel(const float* __restrict__ left,
                            const float* __restrict__ right,
                            float* __restrict__ out)
{
    // Flat id over (n, y, x4): x4 fastest so warps and consecutive CTAs
    // cover contiguous output addresses within each d-plane.
    const int gid = blockIdx.x * THREADS + threadIdx.x;   // < 239616
    const int x4  = gid % W4;
    const int ny  = gid / W4;                             // n*H + y, < 768
    const int d0  = blockIdx.y * D_CHUNK;                 // multiple of 4

    const int x0 = 4 * x4;

    // Left float4 (always in-bounds, aligned).
    const float4 L = reinterpret_cast<const float4*>(
                         left + (size_t)ny * W_DIM)[x4];

    // Window: floats [x0-d0-4, x0-d0+3] of the right row (blocks b, b+1).
    // Covers R[x0-d .. x0+3-d] for d in [d0, d0+3]. Negative blocks clamp
    // to 0 — clamped values feed only mask-zeroed outputs (x < d there).
    const float4* rrow4 = reinterpret_cast<const float4*>(
                              right + (size_t)ny * W_DIM);
    const int b  = x4 - d0 / 4 - 1;      // may be negative, <= 310
    const int b0 = b     < 0 ? 0 : b;
    const int b1 = b + 1 < 0 ? 0 : b + 1;

    float w[8];
    {
        const float4 X = rrow4[b0];
        const float4 Y = rrow4[b1];
        w[0]=X.x; w[1]=X.y; w[2]=X.z; w[3]=X.w;
        w[4]=Y.x; w[5]=Y.y; w[6]=Y.z; w[7]=Y.w;
    }

    const int n = ny / H_DIM;
    const int y = ny % H_DIM;
    float* ob = out + ((size_t)(n * D_DIM + d0) * H_DIM + y) * W_DIM + x0;

    #pragma unroll
    for (int k = 0; k < D_CHUNK; ++k) {
        const int d  = d0 + k;
        const int j0 = 4 - k;            // compile-time window offset

        float4 v;
        v.x = (x0 + 0 >= d) ? fabsf(L.x - w[j0 + 0]) : 0.f;
        v.y = (x0 + 1 >= d) ? fabsf(L.y - w[j0 + 1]) : 0.f;
        v.z = (x0 + 2 >= d) ? fabsf(L.z - w[j0 + 2]) : 0.f;
        v.w = (x0 + 3 >= d) ? fabsf(L.w - w[j0 + 3]) : 0.f;

        stcs4((float4*)(ob + (size_t)k * (H_DIM * W_DIM)), v);
    }
}

extern "C" void kernel_launch(void* const* d_in, const int* in_sizes, int n_in,
                              void* d_out, int out_size)
{
    const float* image1 = (const float*)d_in[0];  // left
    const float* image2 = (const float*)d_in[1];  // right (shifted source)
    float* out = (float*)d_out;

    (void)in_sizes; (void)n_in; (void)out_size;

    dim3 grid(XY_BLKS, D_DIM / D_CHUNK);   // 468 x 32 = 14976 blocks
    dim3 block(THREADS);
    absdiff_costvol_kernel<<<grid, block>>>(image1, image2, out);
}

// round 17
// speedup vs baseline: 1.0547x; 1.0014x over previous
#include <cuda_runtime.h>
#include <cuda_bf16.h>

// AbsDiff cost volume:
//   out[n, d, y, x] = |image1[n,0,y,x] - image2[n,0,y,x-d]|  if x-d >= 0 else 0
// in [2,1,384,1248] fp32, out [2,128,384,1248] fp32. HBM-write-bound (~491MB).
// R17 = R13 body (chain-4 STG.128 .cs, no smem/sync, xy-fastest traversal ->
// concurrent CTAs write contiguous DRAM) with 128-thread CTAs at occ 16:
// same 2048 thr/SM, finer CTA granularity -> higher achieved occupancy
// (R7 precedent: small CTAs hit 88% vs 75% here) and smoother store drain.
// Family results: chain16=71.8, chain8=69.7, chain4/256=69.15, chain4/512=69.7.

#define W_DIM    1248
#define H_DIM    384
#define N_DIM    2
#define D_DIM    128
#define W4       (W_DIM / 4)          // 312
#define THREADS  128                  // 4 warps; occ 16 -> 64 warps/SM
#define D_CHUNK  4                    // per-thread store chain
#define XY_BLKS  ((N_DIM * H_DIM * W4) / THREADS)   // 1872, exact

__device__ __forceinline__ void stcs4(float4* p, float4 v) {
    asm volatile("st.global.cs.v4.f32 [%0], {%1,%2,%3,%4};"
                 :: "l"(p), "f"(v.x), "f"(v.y), "f"(v.z), "f"(v.w) : "memory");
}

__global__ __launch_bounds__(THREADS, 16)
void absdiff_costvol_kernel(const float* __restrict__ left,
                            const float* __restrict__ right,
                            float* __restrict__ out)
{
    // Flat id over (n, y, x4): x4 fastest so warps and consecutive CTAs
    // cover contiguous output addresses within each d-plane.
    const int gid = blockIdx.x * THREADS + threadIdx.x;   // < 239616
    const int x4  = gid % W4;
    const int ny  = gid / W4;                             // n*H + y, < 768
    const int d0  = blockIdx.y * D_CHUNK;                 // multiple of 4

    const int x0 = 4 * x4;

    // Left float4 (always in-bounds, aligned).
    const float4 L = reinterpret_cast<const float4*>(
                         left + (size_t)ny * W_DIM)[x4];

    // Window: floats [x0-d0-4, x0-d0+3] of the right row (blocks b, b+1).
    // Covers R[x0-d .. x0+3-d] for d in [d0, d0+3]. Negative blocks clamp
    // to 0 — clamped values feed only mask-zeroed outputs (x < d there).
    const float4* rrow4 = reinterpret_cast<const float4*>(
                              right + (size_t)ny * W_DIM);
    const int b  = x4 - d0 / 4 - 1;      // may be negative, <= 310
    const int b0 = b     < 0 ? 0 : b;
    const int b1 = b + 1 < 0 ? 0 : b + 1;

    float w[8];
    {
        const float4 X = rrow4[b0];
        const float4 Y = rrow4[b1];
        w[0]=X.x; w[1]=X.y; w[2]=X.z; w[3]=X.w;
        w[4]=Y.x; w[5]=Y.y; w[6]=Y.z; w[7]=Y.w;
    }

    const int n = ny / H_DIM;
    const int y = ny % H_DIM;
    float* ob = out + ((size_t)(n * D_DIM + d0) * H_DIM + y) * W_DIM + x0;

    #pragma unroll
    for (int k = 0; k < D_CHUNK; ++k) {
        const int d  = d0 + k;
        const int j0 = 4 - k;            // compile-time window offset

        float4 v;
        v.x = (x0 + 0 >= d) ? fabsf(L.x - w[j0 + 0]) : 0.f;
        v.y = (x0 + 1 >= d) ? fabsf(L.y - w[j0 + 1]) : 0.f;
        v.z = (x0 + 2 >= d) ? fabsf(L.z - w[j0 + 2]) : 0.f;
        v.w = (x0 + 3 >= d) ? fabsf(L.w - w[j0 + 3]) : 0.f;

        stcs4((float4*)(ob + (size_t)k * (H_DIM * W_DIM)), v);
    }
}

extern "C" void kernel_launch(void* const* d_in, const int* in_sizes, int n_in,
                              void* d_out, int out_size)
{
    const float* image1 = (const float*)d_in[0];  // left
    const float* image2 = (const float*)d_in[1];  // right (shifted source)
    float* out = (float*)d_out;

    (void)in_sizes; (void)n_in; (void)out_size;

    dim3 grid(XY_BLKS, D_DIM / D_CHUNK);   // 1872 x 32 = 59904 blocks
    dim3 block(THREADS);
    absdiff_costvol_kernel<<<grid, block>>>(image1, image2, out);
}